// round 12
// baseline (speedup 1.0000x reference)
#include <cuda_runtime.h>
#include <cuda_fp16.h>

typedef unsigned int u32;

#define NN 40000
#define EE 640000
#define HH 128
#define GG 256
#define CC 10
#define LL 3

#define SB 256
#define SI 4
#define SCHUNK (SB * SI)                      // 1024
#define SNB ((NN + SCHUNK - 1) / SCHUNK)      // 40

#define MT 128                                 // GEMM M tile
#define GEMM_BLOCKS ((NN + MT - 1) / MT)       // 313

// prep kernel block ranges
#define NB_X (NN / 8)                          // 5000, warp per row
#define NB_W 384                               // 6*HH*HH / 256
#define NB_D 157                               // ceil(NN/256)
#define NB_PREP (NB_X + NB_W + NB_D + 1)

// Scratch (allocation-free rule: device globals, device-code references only)
__device__ __half g_xh[NN * HH];
__device__ __half g_aggh[NN * HH];
__device__ __half g_h0[NN * HH];
__device__ __half g_h1[NN * HH];
__device__ signed char g_xq[NN * HH];
__device__ signed char g_q0[NN * HH];
__device__ signed char g_q1[NN * HH];
__device__ float g_sclx[NN];
__device__ float g_scl0[NN];
__device__ float g_scl1[NN];
__device__ __half g_wTh[6][HH * HH];   // [layer*2+(0=rel,1=root)][n][k] fp16
__device__ float g_counts[GG];
__device__ int   g_gstart[GG + 1];
__device__ int   g_deg[NN];
__device__ int   g_rowptr[NN + 1];
__device__ int   g_cursor[NN];
__device__ int   g_srclist[EE];
__device__ int   g_pval[SNB];
__device__ int   g_flag[SNB];

__device__ __forceinline__ const __half* sel_buf_h(int sel) {
    return (sel < 0) ? (const __half*)g_xh
                     : (sel == 0 ? (const __half*)g_h0 : (const __half*)g_h1);
}
__device__ __forceinline__ const signed char* sel_buf_q(int sel) {
    return (sel < 0) ? (const signed char*)g_xq
                     : (sel == 0 ? (const signed char*)g_q0 : (const signed char*)g_q1);
}
__device__ __forceinline__ const float* sel_buf_s(int sel) {
    return (sel < 0) ? (const float*)g_sclx
                     : (sel == 0 ? (const float*)g_scl0 : (const float*)g_scl1);
}

__device__ __forceinline__ void mma_f16(float* d, const u32* a, u32 b0, u32 b1) {
    asm volatile(
        "mma.sync.aligned.m16n8k16.row.col.f32.f16.f16.f32 "
        "{%0,%1,%2,%3}, {%4,%5,%6,%7}, {%8,%9}, {%0,%1,%2,%3};"
        : "+f"(d[0]), "+f"(d[1]), "+f"(d[2]), "+f"(d[3])
        : "r"(a[0]), "r"(a[1]), "r"(a[2]), "r"(a[3]), "r"(b0), "r"(b1));
}

// ---------------------------------------------------------------------------
// Prep: x -> fp16 + per-row int8 | weights transpose->fp16 | zero deg | bounds
// ---------------------------------------------------------------------------
__global__ void __launch_bounds__(256)
prep_kernel(const float* __restrict__ x,
            const float* __restrict__ w_rel, const float* __restrict__ w_root,
            const int* __restrict__ batch) {
    int b = blockIdx.x;
    if (b < NB_X) {
        // warp per row: fp16 copy + per-row absmax + int8 quantize
        int row = b * 8 + (threadIdx.x >> 5);
        int lane = threadIdx.x & 31;
        float4 v = *reinterpret_cast<const float4*>(x + (size_t)row * HH + lane * 4);
        __half2 h0 = __floats2half2_rn(v.x, v.y);
        __half2 h1 = __floats2half2_rn(v.z, v.w);
        uint2 o = make_uint2(*(u32*)&h0, *(u32*)&h1);
        *reinterpret_cast<uint2*>(g_xh + (size_t)row * HH + lane * 4) = o;
        float m = fmaxf(fmaxf(fabsf(v.x), fabsf(v.y)), fmaxf(fabsf(v.z), fabsf(v.w)));
#pragma unroll
        for (int d = 16; d; d >>= 1) m = fmaxf(m, __shfl_xor_sync(0xffffffffu, m, d));
        float inv = (m > 0.f) ? (127.f / m) : 0.f;
        int q0 = __float2int_rn(v.x * inv);
        int q1 = __float2int_rn(v.y * inv);
        int q2 = __float2int_rn(v.z * inv);
        int q3 = __float2int_rn(v.w * inv);
        u32 packed = (q0 & 0xff) | ((q1 & 0xff) << 8) | ((q2 & 0xff) << 16) | ((u32)q3 << 24);
        *reinterpret_cast<u32*>(g_xq + (size_t)row * HH + lane * 4) = packed;
        if (lane == 0) g_sclx[row] = m * (1.f / 127.f);
        return;
    }
    b -= NB_X;
    if (b < NB_W) {
        int idx = b * 256 + threadIdx.x;
        int m = idx / (HH * HH);
        int rem = idx % (HH * HH);
        int n = rem / HH, k = rem % HH;
        int l = m >> 1;
        const float* w = (m & 1) ? (w_root + (size_t)l * HH * HH)
                                 : (w_rel + (size_t)l * HH * HH);
        g_wTh[m][n * HH + k] = __float2half(w[k * HH + n]);
        return;
    }
    b -= NB_W;
    if (b < NB_D) {
        int i = b * 256 + threadIdx.x;
        if (i < NN) g_deg[i] = 0;
        return;
    }
    // bounds block (1 block, 256 threads = GG); also zero scan flags
    int g = threadIdx.x;
    if (g < SNB) g_flag[g] = 0;
    int lo = 0, hi = NN;
    while (lo < hi) {
        int m = (lo + hi) >> 1;
        if (batch[m] < g) lo = m + 1; else hi = m;
    }
    g_gstart[g] = lo;
    if (g == 0) g_gstart[GG] = NN;
    __syncthreads();
    g_counts[g] = (float)(g_gstart[g + 1] - g_gstart[g]);
}

// ---------------------------------------------------------------------------
// CSR build
// ---------------------------------------------------------------------------
__global__ void degree_kernel(const int* __restrict__ ei) {
    int e = blockIdx.x * blockDim.x + threadIdx.x;
    if (e < EE) atomicAdd(&g_deg[ei[EE + e]], 1);
}

// Single-pass scan: block-local scan + decoupled lookback over partials.
// All SNB=40 blocks are resident simultaneously, so spinning is safe.
__global__ void __launch_bounds__(SB) scan_kernel() {
    __shared__ int wsum[SB / 32];
    __shared__ int off_s;
    const int b = blockIdx.x, t = threadIdx.x;
    const int base = b * SCHUNK + t * SI;
    const int lane = t & 31, wid = t >> 5;

    int4 v = make_int4(0, 0, 0, 0);
    if (base + SI <= NN) {
        v = *reinterpret_cast<const int4*>(&g_deg[base]);
    } else {
        if (base + 0 < NN) v.x = g_deg[base + 0];
        if (base + 1 < NN) v.y = g_deg[base + 1];
        if (base + 2 < NN) v.z = g_deg[base + 2];
        if (base + 3 < NN) v.w = g_deg[base + 3];
    }
    int s = v.x + v.y + v.z + v.w;

    int inc = s;
#pragma unroll
    for (int d = 1; d < 32; d <<= 1) {
        int u = __shfl_up_sync(0xffffffffu, inc, d);
        if (lane >= d) inc += u;
    }
    if (lane == 31) wsum[wid] = inc;
    __syncthreads();
    if (t < SB / 32) {
        int ws = wsum[t];
#pragma unroll
        for (int d = 1; d < SB / 32; d <<= 1) {
            int u = __shfl_up_sync(0xffu, ws, d);
            if (t >= d) ws += u;
        }
        wsum[t] = ws;
    }
    __syncthreads();

    // publish block total
    if (t == 0) {
        g_pval[b] = wsum[SB / 32 - 1];
        __threadfence();
        atomicExch(&g_flag[b], 1);
        off_s = 0;
    }
    // lookback (warp 0 lanes cover predecessors)
    if (b > 0 && t < 32) {
        int sum = 0;
        for (int i = t; i < b; i += 32) {
            while (atomicAdd(&g_flag[i], 0) == 0) {}
            sum += atomicAdd(&g_pval[i], 0);
        }
#pragma unroll
        for (int d = 16; d; d >>= 1) sum += __shfl_xor_sync(0xffffffffu, sum, d);
        if (t == 0) off_s = sum;
    }
    __syncthreads();
    const int off = off_s;

    int r = inc - s + (wid ? wsum[wid - 1] : 0) + off;   // global exclusive prefix
    if (base + 0 < NN) { g_rowptr[base + 0] = r; g_cursor[base + 0] = r; }  r += v.x;
    if (base + 1 < NN) { g_rowptr[base + 1] = r; g_cursor[base + 1] = r; }  r += v.y;
    if (base + 2 < NN) { g_rowptr[base + 2] = r; g_cursor[base + 2] = r; }  r += v.z;
    if (base + 3 < NN) { g_rowptr[base + 3] = r; g_cursor[base + 3] = r; }
    if (b == 0 && t == 0) g_rowptr[NN] = EE;
}

__global__ void fill_kernel(const int* __restrict__ ei) {
    int e = blockIdx.x * blockDim.x + threadIdx.x;
    if (e >= EE) return;
    int s = ei[e];
    int d = ei[EE + e];
    int pos = atomicAdd(&g_cursor[d], 1);
    g_srclist[pos] = s;
}

// ---------------------------------------------------------------------------
// Aggregation as gather over int8 rows + per-row scales (fp32 accum, fp16 out)
// one warp per node; each lane owns 4 features (4B per edge per lane).
// ---------------------------------------------------------------------------
__global__ void gather_kernel(int sel) {
    int gid = blockIdx.x * blockDim.x + threadIdx.x;
    int node = gid >> 5;
    int lane = gid & 31;
    if (node >= NN) return;
    const signed char* q = sel_buf_q(sel);
    const float* scl = sel_buf_s(sel);

    int beg = g_rowptr[node];
    int end = g_rowptr[node + 1];
    float4 acc = make_float4(0.f, 0.f, 0.f, 0.f);
    int p = beg;
    for (; p + 2 <= end; p += 2) {
        int s0 = g_srclist[p], s1 = g_srclist[p + 1];
        float c0 = scl[s0], c1 = scl[s1];
        u32 v0 = *reinterpret_cast<const u32*>(q + (size_t)s0 * HH + lane * 4);
        u32 v1 = *reinterpret_cast<const u32*>(q + (size_t)s1 * HH + lane * 4);
        char4 a = *(char4*)&v0;
        char4 b = *(char4*)&v1;
        acc.x += c0 * (float)a.x + c1 * (float)b.x;
        acc.y += c0 * (float)a.y + c1 * (float)b.y;
        acc.z += c0 * (float)a.z + c1 * (float)b.z;
        acc.w += c0 * (float)a.w + c1 * (float)b.w;
    }
    if (p < end) {
        int s0 = g_srclist[p];
        float c0 = scl[s0];
        u32 v0 = *reinterpret_cast<const u32*>(q + (size_t)s0 * HH + lane * 4);
        char4 a = *(char4*)&v0;
        acc.x += c0 * (float)a.x;
        acc.y += c0 * (float)a.y;
        acc.z += c0 * (float)a.z;
        acc.w += c0 * (float)a.w;
    }
    __half2 o0 = __floats2half2_rn(acc.x, acc.y);
    __half2 o1 = __floats2half2_rn(acc.z, acc.w);
    uint2 o = make_uint2(*(u32*)&o0, *(u32*)&o1);
    *reinterpret_cast<uint2*>(g_aggh + (size_t)node * HH + lane * 4) = o;
}

// ---------------------------------------------------------------------------
// Tensor-core layer GEMM (fp16 mma.sync m16n8k16, fp32 accum):
// out = ( [agg | h] @ [wr ; wroot] + b_rel ) * node_scale
// Outputs: fp16 buffer + per-row int8 quantized buffer + row scales.
// ---------------------------------------------------------------------------
__global__ void __launch_bounds__(256)
gemm_layer_mma(int in_sel, int out_sel, int layer,
               const float* __restrict__ brel,
               const int* __restrict__ batch) {
    __shared__ __half As[128][40];
    __shared__ __half Bs[128][40];
    __shared__ int rowmaxi[MT];

    const __half* h    = sel_buf_h(in_sel);
    __half*       out  = (out_sel == 0) ? (__half*)g_h0 : (__half*)g_h1;
    signed char*  qout = (out_sel == 0) ? (signed char*)g_q0 : (signed char*)g_q1;
    float*        sout = (out_sel == 0) ? (float*)g_scl0 : (float*)g_scl1;

    const int tid  = threadIdx.x;
    const int wid  = tid >> 5, lane = tid & 31;
    const int g    = lane >> 2, t4 = lane & 3;
    const int wm   = wid & 3,  wn  = wid >> 2;
    const int row0 = blockIdx.x * MT;
    const int mbase = wm * 32;
    const int nbase = wn * 64;

    if (tid < MT) rowmaxi[tid] = 0;

    float acc[2][8][4];
#pragma unroll
    for (int mf = 0; mf < 2; mf++)
#pragma unroll
        for (int nf = 0; nf < 8; nf++)
#pragma unroll
            for (int q = 0; q < 4; q++) acc[mf][nf][q] = 0.f;

    for (int c = 0; c < 8; c++) {
        const __half* asrc = (c < 4) ? (const __half*)g_aggh : h;
        const __half* bsrc = &g_wTh[layer * 2 + (c < 4 ? 0 : 1)][0];
        const int ks = (c & 3) * 32;

        __syncthreads();
#pragma unroll
        for (int i = 0; i < 2; i++) {
            int f = tid + i * 256;
            int r = f >> 2, q = f & 3;
            uint4 v = make_uint4(0, 0, 0, 0);
            if (row0 + r < NN)
                v = *reinterpret_cast<const uint4*>(asrc + (size_t)(row0 + r) * HH + ks + q * 8);
            *reinterpret_cast<uint4*>(&As[r][q * 8]) = v;
        }
#pragma unroll
        for (int i = 0; i < 2; i++) {
            int f = tid + i * 256;
            int r = f >> 2, q = f & 3;
            uint4 v = *reinterpret_cast<const uint4*>(bsrc + (size_t)r * HH + ks + q * 8);
            *reinterpret_cast<uint4*>(&Bs[r][q * 8]) = v;
        }
        __syncthreads();

#pragma unroll
        for (int k16 = 0; k16 < 2; k16++) {
            const int kk = k16 * 16;
            u32 a[2][4];
#pragma unroll
            for (int mf = 0; mf < 2; mf++) {
                int rm = mbase + mf * 16;
                a[mf][0] = *(const u32*)&As[rm + g][kk + 2 * t4];
                a[mf][1] = *(const u32*)&As[rm + g + 8][kk + 2 * t4];
                a[mf][2] = *(const u32*)&As[rm + g][kk + 2 * t4 + 8];
                a[mf][3] = *(const u32*)&As[rm + g + 8][kk + 2 * t4 + 8];
            }
#pragma unroll
            for (int nf = 0; nf < 8; nf++) {
                int nrow = nbase + nf * 8 + g;
                u32 b0 = *(const u32*)&Bs[nrow][kk + 2 * t4];
                u32 b1 = *(const u32*)&Bs[nrow][kk + 2 * t4 + 8];
                mma_f16(acc[0][nf], a[0], b0, b1);
                mma_f16(acc[1][nf], a[1], b0, b1);
            }
        }
    }

    // ---- Epilogue: finalize (bias + node_scale) in place, row maxima ----
    __syncthreads();   // rowmaxi init visible; As/Bs no longer needed
#pragma unroll
    for (int mf = 0; mf < 2; mf++) {
        int r0 = row0 + mbase + mf * 16 + g;
        int r1 = r0 + 8;
        float s0 = 0.f, s1 = 0.f;
        if (r0 < NN) { float cnt = g_counts[batch[r0]]; s0 = (cnt > 0.f) ? (1.f / cnt) : 0.f; }
        if (r1 < NN) { float cnt = g_counts[batch[r1]]; s1 = (cnt > 0.f) ? (1.f / cnt) : 0.f; }
        float m0 = 0.f, m1 = 0.f;
#pragma unroll
        for (int nf = 0; nf < 8; nf++) {
            int col = nbase + nf * 8 + t4 * 2;
            float b0 = __ldg(&brel[col]), b1 = __ldg(&brel[col + 1]);
            acc[mf][nf][0] = (acc[mf][nf][0] + b0) * s0;
            acc[mf][nf][1] = (acc[mf][nf][1] + b1) * s0;
            acc[mf][nf][2] = (acc[mf][nf][2] + b0) * s1;
            acc[mf][nf][3] = (acc[mf][nf][3] + b1) * s1;
            m0 = fmaxf(m0, fmaxf(fabsf(acc[mf][nf][0]), fabsf(acc[mf][nf][1])));
            m1 = fmaxf(m1, fmaxf(fabsf(acc[mf][nf][2]), fabsf(acc[mf][nf][3])));
        }
        // reduce over the 4 t4-lanes of this row
        m0 = fmaxf(m0, __shfl_xor_sync(0xffffffffu, m0, 1));
        m0 = fmaxf(m0, __shfl_xor_sync(0xffffffffu, m0, 2));
        m1 = fmaxf(m1, __shfl_xor_sync(0xffffffffu, m1, 1));
        m1 = fmaxf(m1, __shfl_xor_sync(0xffffffffu, m1, 2));
        if (t4 == 0) {
            atomicMax(&rowmaxi[mbase + mf * 16 + g], __float_as_int(m0));
            atomicMax(&rowmaxi[mbase + mf * 16 + g + 8], __float_as_int(m1));
        }
    }
    __syncthreads();

    // ---- Stores: fp16 + int8 + row scale ----
#pragma unroll
    for (int mf = 0; mf < 2; mf++) {
        int r0 = row0 + mbase + mf * 16 + g;
        int r1 = r0 + 8;
        float M0 = __int_as_float(rowmaxi[mbase + mf * 16 + g]);
        float M1 = __int_as_float(rowmaxi[mbase + mf * 16 + g + 8]);
        float i0 = (M0 > 0.f) ? (127.f / M0) : 0.f;
        float i1 = (M1 > 0.f) ? (127.f / M1) : 0.f;
        if (wn == 0 && t4 == 0) {
            if (r0 < NN) sout[r0] = M0 * (1.f / 127.f);
            if (r1 < NN) sout[r1] = M1 * (1.f / 127.f);
        }
#pragma unroll
        for (int nf = 0; nf < 8; nf++) {
            int col = nbase + nf * 8 + t4 * 2;
            if (r0 < NN) {
                __half2 o = __floats2half2_rn(acc[mf][nf][0], acc[mf][nf][1]);
                *reinterpret_cast<__half2*>(out + (size_t)r0 * HH + col) = o;
                int qa = __float2int_rn(acc[mf][nf][0] * i0);
                int qb = __float2int_rn(acc[mf][nf][1] * i0);
                *reinterpret_cast<short*>(qout + (size_t)r0 * HH + col) =
                    (short)((qa & 0xff) | ((qb & 0xff) << 8));
            }
            if (r1 < NN) {
                __half2 o = __floats2half2_rn(acc[mf][nf][2], acc[mf][nf][3]);
                *reinterpret_cast<__half2*>(out + (size_t)r1 * HH + col) = o;
                int qa = __float2int_rn(acc[mf][nf][2] * i1);
                int qb = __float2int_rn(acc[mf][nf][3] * i1);
                *reinterpret_cast<short*>(qout + (size_t)r1 * HH + col) =
                    (short)((qa & 0xff) | ((qb & 0xff) << 8));
            }
        }
    }
}

// ---------------------------------------------------------------------------
// Fused head: mean-pool (fp16 in, fp32 accum), relu MLP, log_softmax.
// ---------------------------------------------------------------------------
__global__ void __launch_bounds__(HH)
head_kernel(int sel,
            const float* __restrict__ w1, const float* __restrict__ b1,
            const float* __restrict__ w2, const float* __restrict__ b2,
            float* __restrict__ out) {
    __shared__ float p[HH];
    __shared__ float hv[HH];
    __shared__ float lg[CC];
    __shared__ float m_s, ls_s;

    const int g = blockIdx.x;
    const int tid = threadIdx.x;
    const __half* h = sel_buf_h(sel);

    int lo = g_gstart[g], hi = g_gstart[g + 1];
    float inv = (hi > lo) ? (1.f / (float)(hi - lo)) : 0.f;
    float acc0 = 0.f;
    for (int r = lo; r < hi; r++) acc0 += __half2float(h[(size_t)r * HH + tid]);
    p[tid] = acc0 * inv;
    __syncthreads();

    float acc = b1[tid];
#pragma unroll 8
    for (int k = 0; k < HH; k++) acc += p[k] * w1[k * HH + tid];
    hv[tid] = fmaxf(acc, 0.f);
    __syncthreads();

    if (tid < CC) {
        float l = b2[tid];
#pragma unroll 8
        for (int k = 0; k < HH; k++) l += hv[k] * w2[k * CC + tid];
        lg[tid] = l;
    }
    __syncthreads();

    if (tid == 0) {
        float m = lg[0];
#pragma unroll
        for (int i = 1; i < CC; i++) m = fmaxf(m, lg[i]);
        float s = 0.f;
#pragma unroll
        for (int i = 0; i < CC; i++) s += expf(lg[i] - m);
        m_s = m;
        ls_s = logf(s);
    }
    __syncthreads();
    if (tid < CC) out[g * CC + tid] = lg[tid] - m_s - ls_s;
}

// ---------------------------------------------------------------------------
extern "C" void kernel_launch(void* const* d_in, const int* in_sizes, int n_in,
                              void* d_out, int out_size) {
    const float* x      = (const float*)d_in[0];
    const int*   ei     = (const int*)d_in[1];
    const int*   batch  = (const int*)d_in[2];
    const float* w_rel  = (const float*)d_in[3];
    const float* b_rel  = (const float*)d_in[4];
    const float* w_root = (const float*)d_in[5];
    const float* w1     = (const float*)d_in[6];
    const float* b1     = (const float*)d_in[7];
    const float* w2     = (const float*)d_in[8];
    const float* b2     = (const float*)d_in[9];
    float* out = (float*)d_out;

    // Prep: x->fp16+int8, weights->fp16 transposed, zero deg/flags, bounds
    prep_kernel<<<NB_PREP, 256>>>(x, w_rel, w_root, batch);

    // CSR build (edge structure reused across 3 layers)
    degree_kernel<<<(EE + 255) / 256, 256>>>(ei);
    scan_kernel<<<SNB, SB>>>();
    fill_kernel<<<(EE + 255) / 256, 256>>>(ei);

    // 3 GraphConv layers (sel: -1 = x, 0 = buf0, 1 = buf1)
    int cur_sel = -1;
    for (int l = 0; l < LL; l++) {
        gather_kernel<<<(NN * 32 + 255) / 256, 256>>>(cur_sel);
        int out_sel = l & 1;
        gemm_layer_mma<<<GEMM_BLOCKS, 256>>>(cur_sel, out_sel, l,
                                             b_rel + (size_t)l * HH, batch);
        cur_sel = out_sel;
    }

    // Fused mean-pool + MLP head
    head_kernel<<<GG, HH>>>(cur_sel, w1, b1, w2, b2, out);
}

// round 15
// speedup vs baseline: 1.2798x; 1.2798x over previous
#include <cuda_runtime.h>
#include <cuda_fp16.h>

typedef unsigned int u32;

#define NN 40000
#define EE 640000
#define HH 128
#define GG 256
#define CC 10
#define LL 3

#define SB 256
#define SI 4
#define SCHUNK (SB * SI)                      // 1024
#define SNB ((NN + SCHUNK - 1) / SCHUNK)      // 40

#define MT 128                                 // GEMM M tile
#define GEMM_BLOCKS ((NN + MT - 1) / MT)       // 313

// prep kernel block ranges
#define NB_X 5000                              // NN*HH/4 / 256
#define NB_W 384                               // 6*HH*HH / 256
#define NB_D 157                               // ceil(NN/256)
#define NB_PREP (NB_X + NB_W + NB_D + 1)

// Scratch (allocation-free rule: device globals, device-code references only)
__device__ __half g_xh[NN * HH];
__device__ __half g_aggh[NN * HH];
__device__ __half g_h0[NN * HH];
__device__ __half g_h1[NN * HH];
__device__ __half g_wTh[6][HH * HH];   // [layer*2+(0=rel,1=root)][n][k] fp16
__device__ float g_counts[GG];
__device__ int   g_gstart[GG + 1];
__device__ int   g_deg[NN];
__device__ int   g_rowptr[NN + 1];
__device__ int   g_cursor[NN];
__device__ int   g_srclist[EE];
__device__ int   g_pval[SNB];
__device__ int   g_flag[SNB];

__device__ __forceinline__ const __half* sel_buf_h(int sel) {
    return (sel < 0) ? (const __half*)g_xh
                     : (sel == 0 ? (const __half*)g_h0 : (const __half*)g_h1);
}

__device__ __forceinline__ void mma_f16(float* d, const u32* a, u32 b0, u32 b1) {
    asm volatile(
        "mma.sync.aligned.m16n8k16.row.col.f32.f16.f16.f32 "
        "{%0,%1,%2,%3}, {%4,%5,%6,%7}, {%8,%9}, {%0,%1,%2,%3};"
        : "+f"(d[0]), "+f"(d[1]), "+f"(d[2]), "+f"(d[3])
        : "r"(a[0]), "r"(a[1]), "r"(a[2]), "r"(a[3]), "r"(b0), "r"(b1));
}

// ---------------------------------------------------------------------------
// Prep: convert x->fp16 | transpose+convert weights | zero degrees | bounds.
// ---------------------------------------------------------------------------
__global__ void __launch_bounds__(256)
prep_kernel(const float* __restrict__ x,
            const float* __restrict__ w_rel, const float* __restrict__ w_root,
            const int* __restrict__ batch) {
    int b = blockIdx.x;
    if (b < NB_X) {
        int i = b * 256 + threadIdx.x;
        float4 v = reinterpret_cast<const float4*>(x)[i];
        __half2 h0 = __floats2half2_rn(v.x, v.y);
        __half2 h1 = __floats2half2_rn(v.z, v.w);
        uint2 o = make_uint2(*(u32*)&h0, *(u32*)&h1);
        reinterpret_cast<uint2*>(g_xh)[i] = o;
        return;
    }
    b -= NB_X;
    if (b < NB_W) {
        int idx = b * 256 + threadIdx.x;
        int m = idx / (HH * HH);
        int rem = idx % (HH * HH);
        int n = rem / HH, k = rem % HH;
        int l = m >> 1;
        const float* w = (m & 1) ? (w_root + (size_t)l * HH * HH)
                                 : (w_rel + (size_t)l * HH * HH);
        g_wTh[m][n * HH + k] = __float2half(w[k * HH + n]);
        return;
    }
    b -= NB_W;
    if (b < NB_D) {
        int i = b * 256 + threadIdx.x;
        if (i < NN) g_deg[i] = 0;
        return;
    }
    // bounds block (1 block, 256 threads = GG); also zero scan flags
    int g = threadIdx.x;
    if (g < SNB) g_flag[g] = 0;
    int lo = 0, hi = NN;
    while (lo < hi) {
        int m = (lo + hi) >> 1;
        if (batch[m] < g) lo = m + 1; else hi = m;
    }
    g_gstart[g] = lo;
    if (g == 0) g_gstart[GG] = NN;
    __syncthreads();
    g_counts[g] = (float)(g_gstart[g + 1] - g_gstart[g]);
}

// ---------------------------------------------------------------------------
// CSR build: degree histogram (4 edges/thread), single-pass scan, fill
// ---------------------------------------------------------------------------
__global__ void degree_kernel(const int* __restrict__ ei) {
    int base = (blockIdx.x * blockDim.x + threadIdx.x) * 4;
    if (base >= EE) return;
    int4 d = *reinterpret_cast<const int4*>(ei + EE + base);
    atomicAdd(&g_deg[d.x], 1);
    atomicAdd(&g_deg[d.y], 1);
    atomicAdd(&g_deg[d.z], 1);
    atomicAdd(&g_deg[d.w], 1);
}

// Single-pass scan: block-local scan + decoupled lookback over partials.
// All SNB=40 blocks are resident simultaneously, so spinning is safe.
__global__ void __launch_bounds__(SB) scan_kernel() {
    __shared__ int wsum[SB / 32];
    __shared__ int off_s;
    const int b = blockIdx.x, t = threadIdx.x;
    const int base = b * SCHUNK + t * SI;
    const int lane = t & 31, wid = t >> 5;

    int4 v = make_int4(0, 0, 0, 0);
    if (base + SI <= NN) {
        v = *reinterpret_cast<const int4*>(&g_deg[base]);
    } else {
        if (base + 0 < NN) v.x = g_deg[base + 0];
        if (base + 1 < NN) v.y = g_deg[base + 1];
        if (base + 2 < NN) v.z = g_deg[base + 2];
        if (base + 3 < NN) v.w = g_deg[base + 3];
    }
    int s = v.x + v.y + v.z + v.w;

    int inc = s;
#pragma unroll
    for (int d = 1; d < 32; d <<= 1) {
        int u = __shfl_up_sync(0xffffffffu, inc, d);
        if (lane >= d) inc += u;
    }
    if (lane == 31) wsum[wid] = inc;
    __syncthreads();
    if (t < SB / 32) {
        int ws = wsum[t];
#pragma unroll
        for (int d = 1; d < SB / 32; d <<= 1) {
            int u = __shfl_up_sync(0xffu, ws, d);
            if (t >= d) ws += u;
        }
        wsum[t] = ws;
    }
    __syncthreads();

    // publish block total
    if (t == 0) {
        g_pval[b] = wsum[SB / 32 - 1];
        __threadfence();
        atomicExch(&g_flag[b], 1);
        off_s = 0;
    }
    // lookback (warp 0 lanes cover predecessors)
    if (b > 0 && t < 32) {
        int sum = 0;
        for (int i = t; i < b; i += 32) {
            while (atomicAdd(&g_flag[i], 0) == 0) {}
            sum += atomicAdd(&g_pval[i], 0);
        }
#pragma unroll
        for (int d = 16; d; d >>= 1) sum += __shfl_xor_sync(0xffffffffu, sum, d);
        if (t == 0) off_s = sum;
    }
    __syncthreads();
    const int off = off_s;

    int r = inc - s + (wid ? wsum[wid - 1] : 0) + off;   // global exclusive prefix
    if (base + 0 < NN) { g_rowptr[base + 0] = r; g_cursor[base + 0] = r; }  r += v.x;
    if (base + 1 < NN) { g_rowptr[base + 1] = r; g_cursor[base + 1] = r; }  r += v.y;
    if (base + 2 < NN) { g_rowptr[base + 2] = r; g_cursor[base + 2] = r; }  r += v.z;
    if (base + 3 < NN) { g_rowptr[base + 3] = r; g_cursor[base + 3] = r; }
    if (b == 0 && t == 0) g_rowptr[NN] = EE;
}

// Fill CSR src lists, 4 edges/thread for atomic-latency overlap.
__global__ void fill_kernel(const int* __restrict__ ei) {
    int base = (blockIdx.x * blockDim.x + threadIdx.x) * 4;
    if (base >= EE) return;
    int4 s = *reinterpret_cast<const int4*>(ei + base);
    int4 d = *reinterpret_cast<const int4*>(ei + EE + base);
    int p0 = atomicAdd(&g_cursor[d.x], 1);
    int p1 = atomicAdd(&g_cursor[d.y], 1);
    int p2 = atomicAdd(&g_cursor[d.z], 1);
    int p3 = atomicAdd(&g_cursor[d.w], 1);
    g_srclist[p0] = s.x;
    g_srclist[p1] = s.y;
    g_srclist[p2] = s.z;
    g_srclist[p3] = s.w;
}

// ---------------------------------------------------------------------------
// Aggregation as gather (fp16 in, fp32 accum, fp16 out), unroll-4:
// one warp per node, each lane owns 4 features (8B per edge per lane).
// ---------------------------------------------------------------------------
__global__ void gather_kernel(int sel) {
    int gid = blockIdx.x * blockDim.x + threadIdx.x;
    int node = gid >> 5;
    int lane = gid & 31;
    if (node >= NN) return;
    const __half* h = sel_buf_h(sel);

    int beg = g_rowptr[node];
    int end = g_rowptr[node + 1];
    float2 accA = make_float2(0.f, 0.f);
    float2 accB = make_float2(0.f, 0.f);
    int p = beg;
    for (; p + 4 <= end; p += 4) {
        int s0 = g_srclist[p],     s1 = g_srclist[p + 1];
        int s2 = g_srclist[p + 2], s3 = g_srclist[p + 3];
        uint2 v0 = *reinterpret_cast<const uint2*>(h + (size_t)s0 * HH + lane * 4);
        uint2 v1 = *reinterpret_cast<const uint2*>(h + (size_t)s1 * HH + lane * 4);
        uint2 v2 = *reinterpret_cast<const uint2*>(h + (size_t)s2 * HH + lane * 4);
        uint2 v3 = *reinterpret_cast<const uint2*>(h + (size_t)s3 * HH + lane * 4);
        float2 a0 = __half22float2(*(__half2*)&v0.x), a1 = __half22float2(*(__half2*)&v0.y);
        float2 b0 = __half22float2(*(__half2*)&v1.x), b1 = __half22float2(*(__half2*)&v1.y);
        float2 c0 = __half22float2(*(__half2*)&v2.x), c1 = __half22float2(*(__half2*)&v2.y);
        float2 d0 = __half22float2(*(__half2*)&v3.x), d1 = __half22float2(*(__half2*)&v3.y);
        accA.x += (a0.x + b0.x) + (c0.x + d0.x);
        accA.y += (a0.y + b0.y) + (c0.y + d0.y);
        accB.x += (a1.x + b1.x) + (c1.x + d1.x);
        accB.y += (a1.y + b1.y) + (c1.y + d1.y);
    }
    for (; p < end; p++) {
        int s0 = g_srclist[p];
        uint2 v0 = *reinterpret_cast<const uint2*>(h + (size_t)s0 * HH + lane * 4);
        float2 a0 = __half22float2(*(__half2*)&v0.x);
        float2 a1 = __half22float2(*(__half2*)&v0.y);
        accA.x += a0.x;  accA.y += a0.y;
        accB.x += a1.x;  accB.y += a1.y;
    }
    __half2 o0 = __floats2half2_rn(accA.x, accA.y);
    __half2 o1 = __floats2half2_rn(accB.x, accB.y);
    uint2 o = make_uint2(*(u32*)&o0, *(u32*)&o1);
    *reinterpret_cast<uint2*>(g_aggh + (size_t)node * HH + lane * 4) = o;
}

// ---------------------------------------------------------------------------
// Tensor-core layer GEMM (fp16 mma.sync m16n8k16, fp32 accum):
// out = ( [agg | h] @ [wr ; wroot] + b_rel ) * node_scale   (fp16 out)
// Block 256 thr = 8 warps (4 M x 2 N). M-tile 128, N=128, K=256 in 8 chunks
// of 32 (2 k16 steps each). Per warp: 2 M-frags x 8 N-frags.
// ---------------------------------------------------------------------------
__global__ void __launch_bounds__(256)
gemm_layer_mma(int in_sel, int out_sel, int layer,
               const float* __restrict__ brel,
               const int* __restrict__ batch) {
    __shared__ __half As[128][40];   // 32 data + 8 pad halves
    __shared__ __half Bs[128][40];

    const __half* h   = sel_buf_h(in_sel);
    __half*       out = (out_sel == 0) ? (__half*)g_h0 : (__half*)g_h1;

    const int tid  = threadIdx.x;
    const int wid  = tid >> 5, lane = tid & 31;
    const int g    = lane >> 2, t4 = lane & 3;
    const int wm   = wid & 3,  wn  = wid >> 2;
    const int row0 = blockIdx.x * MT;
    const int mbase = wm * 32;
    const int nbase = wn * 64;

    float acc[2][8][4];
#pragma unroll
    for (int mf = 0; mf < 2; mf++)
#pragma unroll
        for (int nf = 0; nf < 8; nf++)
#pragma unroll
            for (int q = 0; q < 4; q++) acc[mf][nf][q] = 0.f;

    for (int c = 0; c < 8; c++) {
        const __half* asrc = (c < 4) ? (const __half*)g_aggh : h;
        const __half* bsrc = &g_wTh[layer * 2 + (c < 4 ? 0 : 1)][0];
        const int ks = (c & 3) * 32;

        __syncthreads();
        // A chunk: 128 rows x 32 halves (64B/row) = 512 x 16B, 2 per thread
#pragma unroll
        for (int i = 0; i < 2; i++) {
            int f = tid + i * 256;           // 0..511
            int r = f >> 2, q = f & 3;       // row, 16B unit
            uint4 v = make_uint4(0, 0, 0, 0);
            if (row0 + r < NN)
                v = *reinterpret_cast<const uint4*>(asrc + (size_t)(row0 + r) * HH + ks + q * 8);
            *reinterpret_cast<uint4*>(&As[r][q * 8]) = v;
        }
        // B chunk: 128 n-rows x 32 k-halves from [n][k] fp16 weights
#pragma unroll
        for (int i = 0; i < 2; i++) {
            int f = tid + i * 256;
            int r = f >> 2, q = f & 3;
            uint4 v = *reinterpret_cast<const uint4*>(bsrc + (size_t)r * HH + ks + q * 8);
            *reinterpret_cast<uint4*>(&Bs[r][q * 8]) = v;
        }
        __syncthreads();

#pragma unroll
        for (int k16 = 0; k16 < 2; k16++) {
            const int kk = k16 * 16;
            u32 a[2][4];
#pragma unroll
            for (int mf = 0; mf < 2; mf++) {
                int rm = mbase + mf * 16;
                a[mf][0] = *(const u32*)&As[rm + g][kk + 2 * t4];
                a[mf][1] = *(const u32*)&As[rm + g + 8][kk + 2 * t4];
                a[mf][2] = *(const u32*)&As[rm + g][kk + 2 * t4 + 8];
                a[mf][3] = *(const u32*)&As[rm + g + 8][kk + 2 * t4 + 8];
            }
#pragma unroll
            for (int nf = 0; nf < 8; nf++) {
                int nrow = nbase + nf * 8 + g;
                u32 b0 = *(const u32*)&Bs[nrow][kk + 2 * t4];
                u32 b1 = *(const u32*)&Bs[nrow][kk + 2 * t4 + 8];
                mma_f16(acc[0][nf], a[0], b0, b1);
                mma_f16(acc[1][nf], a[1], b0, b1);
            }
        }
    }

    // Epilogue: +bias, *node_scale (fp32), convert to fp16, 4B stores
#pragma unroll
    for (int mf = 0; mf < 2; mf++) {
        int r0 = row0 + mbase + mf * 16 + g;
        int r1 = r0 + 8;
        float s0 = 0.f, s1 = 0.f;
        if (r0 < NN) { float cnt = g_counts[batch[r0]]; s0 = (cnt > 0.f) ? (1.f / cnt) : 0.f; }
        if (r1 < NN) { float cnt = g_counts[batch[r1]]; s1 = (cnt > 0.f) ? (1.f / cnt) : 0.f; }
#pragma unroll
        for (int nf = 0; nf < 8; nf++) {
            int col = nbase + nf * 8 + t4 * 2;
            float b0 = __ldg(&brel[col]), b1 = __ldg(&brel[col + 1]);
            if (r0 < NN) {
                __half2 o = __floats2half2_rn((acc[mf][nf][0] + b0) * s0,
                                              (acc[mf][nf][1] + b1) * s0);
                *reinterpret_cast<__half2*>(out + (size_t)r0 * HH + col) = o;
            }
            if (r1 < NN) {
                __half2 o = __floats2half2_rn((acc[mf][nf][2] + b0) * s1,
                                              (acc[mf][nf][3] + b1) * s1);
                *reinterpret_cast<__half2*>(out + (size_t)r1 * HH + col) = o;
            }
        }
    }
}

// ---------------------------------------------------------------------------
// Fused head: mean-pool (fp16 in, fp32 accum), relu MLP, log_softmax.
// ---------------------------------------------------------------------------
__global__ void __launch_bounds__(HH)
head_kernel(int sel,
            const float* __restrict__ w1, const float* __restrict__ b1,
            const float* __restrict__ w2, const float* __restrict__ b2,
            float* __restrict__ out) {
    __shared__ float p[HH];
    __shared__ float hv[HH];
    __shared__ float lg[CC];
    __shared__ float m_s, ls_s;

    const int g = blockIdx.x;
    const int tid = threadIdx.x;
    const __half* h = sel_buf_h(sel);

    int lo = g_gstart[g], hi = g_gstart[g + 1];
    float inv = (hi > lo) ? (1.f / (float)(hi - lo)) : 0.f;
    float acc0 = 0.f;
    for (int r = lo; r < hi; r++) acc0 += __half2float(h[(size_t)r * HH + tid]);
    p[tid] = acc0 * inv;
    __syncthreads();

    float acc = b1[tid];
#pragma unroll 8
    for (int k = 0; k < HH; k++) acc += p[k] * w1[k * HH + tid];
    hv[tid] = fmaxf(acc, 0.f);
    __syncthreads();

    if (tid < CC) {
        float l = b2[tid];
#pragma unroll 8
        for (int k = 0; k < HH; k++) l += hv[k] * w2[k * CC + tid];
        lg[tid] = l;
    }
    __syncthreads();

    if (tid == 0) {
        float m = lg[0];
#pragma unroll
        for (int i = 1; i < CC; i++) m = fmaxf(m, lg[i]);
        float s = 0.f;
#pragma unroll
        for (int i = 0; i < CC; i++) s += expf(lg[i] - m);
        m_s = m;
        ls_s = logf(s);
    }
    __syncthreads();
    if (tid < CC) out[g * CC + tid] = lg[tid] - m_s - ls_s;
}

// ---------------------------------------------------------------------------
extern "C" void kernel_launch(void* const* d_in, const int* in_sizes, int n_in,
                              void* d_out, int out_size) {
    const float* x      = (const float*)d_in[0];
    const int*   ei     = (const int*)d_in[1];
    const int*   batch  = (const int*)d_in[2];
    const float* w_rel  = (const float*)d_in[3];
    const float* b_rel  = (const float*)d_in[4];
    const float* w_root = (const float*)d_in[5];
    const float* w1     = (const float*)d_in[6];
    const float* b1     = (const float*)d_in[7];
    const float* w2     = (const float*)d_in[8];
    const float* b2     = (const float*)d_in[9];
    float* out = (float*)d_out;

    // Prep: x->fp16, weights transpose->fp16, zero degrees/flags, bounds
    prep_kernel<<<NB_PREP, 256>>>(x, w_rel, w_root, batch);

    // CSR build (edge structure reused across 3 layers)
    degree_kernel<<<(EE / 4 + 255) / 256, 256>>>(ei);
    scan_kernel<<<SNB, SB>>>();
    fill_kernel<<<(EE / 4 + 255) / 256, 256>>>(ei);

    // 3 GraphConv layers (sel: -1 = x(fp16), 0 = g_h0, 1 = g_h1)
    int cur_sel = -1;
    for (int l = 0; l < LL; l++) {
        gather_kernel<<<(NN * 32 + 255) / 256, 256>>>(cur_sel);
        int out_sel = l & 1;
        gemm_layer_mma<<<GEMM_BLOCKS, 256>>>(cur_sel, out_sel, l,
                                             b_rel + (size_t)l * HH, batch);
        cur_sel = out_sel;
    }

    // Fused mean-pool + MLP head
    head_kernel<<<GG, HH>>>(cur_sel, w1, b1, w2, b2, out);
}

// round 17
// speedup vs baseline: 1.3066x; 1.0209x over previous
#include <cuda_runtime.h>
#include <cuda_fp16.h>

typedef unsigned int u32;

#define NN 40000
#define EE 640000
#define HH 128
#define GG 256
#define CC 10
#define LL 3

#define SB 256
#define SI 4
#define SCHUNK (SB * SI)                      // 1024
#define SNB ((NN + SCHUNK - 1) / SCHUNK)      // 40

#define MT 128                                 // GEMM M tile
#define GEMM_BLOCKS ((NN + MT - 1) / MT)       // 313

// prep kernel block ranges: x-convert | weight transpose | degree hist | bounds
#define NB_X 5000                              // NN*HH/4 / 256
#define NB_W 384                               // 6*HH*HH / 256
#define NB_E 2500                              // EE / 256, one edge per thread
#define NB_PREP (NB_X + NB_W + NB_E + 1)

// Scratch (allocation-free rule: device globals, device-code references only)
// NOTE: g_deg is zero at module load and re-zeroed by fill_kernel every launch,
// so prep's degree histogram can rely on g_deg == 0 at launch entry.
__device__ __half g_xh[NN * HH];
__device__ __half g_aggh[NN * HH];
__device__ __half g_h0[NN * HH];
__device__ __half g_h1[NN * HH];
__device__ __half g_wTh[6][HH * HH];   // [layer*2+(0=rel,1=root)][n][k] fp16
__device__ float g_counts[GG];
__device__ int   g_gstart[GG + 1];
__device__ int   g_deg[NN];
__device__ int   g_rowptr[NN + 1];
__device__ int   g_cursor[NN];
__device__ int   g_srclist[EE];
__device__ int   g_pval[SNB];
__device__ int   g_flag[SNB];

__device__ __forceinline__ const __half* sel_buf_h(int sel) {
    return (sel < 0) ? (const __half*)g_xh
                     : (sel == 0 ? (const __half*)g_h0 : (const __half*)g_h1);
}

__device__ __forceinline__ void mma_f16(float* d, const u32* a, u32 b0, u32 b1) {
    asm volatile(
        "mma.sync.aligned.m16n8k16.row.col.f32.f16.f16.f32 "
        "{%0,%1,%2,%3}, {%4,%5,%6,%7}, {%8,%9}, {%0,%1,%2,%3};"
        : "+f"(d[0]), "+f"(d[1]), "+f"(d[2]), "+f"(d[3])
        : "r"(a[0]), "r"(a[1]), "r"(a[2]), "r"(a[3]), "r"(b0), "r"(b1));
}

// ---------------------------------------------------------------------------
// Prep: convert x->fp16 | transpose+convert weights | degree hist | bounds.
// Degree histogram relies on g_deg == 0 at entry (see note above).
// ---------------------------------------------------------------------------
__global__ void __launch_bounds__(256)
prep_kernel(const float* __restrict__ x,
            const float* __restrict__ w_rel, const float* __restrict__ w_root,
            const int* __restrict__ ei, const int* __restrict__ batch) {
    int b = blockIdx.x;
    if (b < NB_X) {
        int i = b * 256 + threadIdx.x;
        float4 v = reinterpret_cast<const float4*>(x)[i];
        __half2 h0 = __floats2half2_rn(v.x, v.y);
        __half2 h1 = __floats2half2_rn(v.z, v.w);
        uint2 o = make_uint2(*(u32*)&h0, *(u32*)&h1);
        reinterpret_cast<uint2*>(g_xh)[i] = o;
        return;
    }
    b -= NB_X;
    if (b < NB_W) {
        int idx = b * 256 + threadIdx.x;
        int m = idx / (HH * HH);
        int rem = idx % (HH * HH);
        int n = rem / HH, k = rem % HH;
        int l = m >> 1;
        const float* w = (m & 1) ? (w_root + (size_t)l * HH * HH)
                                 : (w_rel + (size_t)l * HH * HH);
        g_wTh[m][n * HH + k] = __float2half(w[k * HH + n]);
        return;
    }
    b -= NB_W;
    if (b < NB_E) {
        int e = b * 256 + threadIdx.x;
        if (e < EE) atomicAdd(&g_deg[ei[EE + e]], 1);
        return;
    }
    // bounds block (1 block, 256 threads = GG); also zero scan flags
    int g = threadIdx.x;
    if (g < SNB) g_flag[g] = 0;
    int lo = 0, hi = NN;
    while (lo < hi) {
        int m = (lo + hi) >> 1;
        if (batch[m] < g) lo = m + 1; else hi = m;
    }
    g_gstart[g] = lo;
    if (g == 0) g_gstart[GG] = NN;
    __syncthreads();
    g_counts[g] = (float)(g_gstart[g + 1] - g_gstart[g]);
}

// ---------------------------------------------------------------------------
// Single-pass scan: block-local scan + decoupled lookback over partials.
// All SNB=40 blocks are resident simultaneously, so spinning is safe.
// ---------------------------------------------------------------------------
__global__ void __launch_bounds__(SB) scan_kernel() {
    __shared__ int wsum[SB / 32];
    __shared__ int off_s;
    const int b = blockIdx.x, t = threadIdx.x;
    const int base = b * SCHUNK + t * SI;
    const int lane = t & 31, wid = t >> 5;

    int4 v = make_int4(0, 0, 0, 0);
    if (base + SI <= NN) {
        v = *reinterpret_cast<const int4*>(&g_deg[base]);
    } else {
        if (base + 0 < NN) v.x = g_deg[base + 0];
        if (base + 1 < NN) v.y = g_deg[base + 1];
        if (base + 2 < NN) v.z = g_deg[base + 2];
        if (base + 3 < NN) v.w = g_deg[base + 3];
    }
    int s = v.x + v.y + v.z + v.w;

    int inc = s;
#pragma unroll
    for (int d = 1; d < 32; d <<= 1) {
        int u = __shfl_up_sync(0xffffffffu, inc, d);
        if (lane >= d) inc += u;
    }
    if (lane == 31) wsum[wid] = inc;
    __syncthreads();
    if (t < SB / 32) {
        int ws = wsum[t];
#pragma unroll
        for (int d = 1; d < SB / 32; d <<= 1) {
            int u = __shfl_up_sync(0xffu, ws, d);
            if (t >= d) ws += u;
        }
        wsum[t] = ws;
    }
    __syncthreads();

    // publish block total
    if (t == 0) {
        g_pval[b] = wsum[SB / 32 - 1];
        __threadfence();
        atomicExch(&g_flag[b], 1);
        off_s = 0;
    }
    // lookback (warp 0 lanes cover predecessors)
    if (b > 0 && t < 32) {
        int sum = 0;
        for (int i = t; i < b; i += 32) {
            while (atomicAdd(&g_flag[i], 0) == 0) {}
            sum += atomicAdd(&g_pval[i], 0);
        }
#pragma unroll
        for (int d = 16; d; d >>= 1) sum += __shfl_xor_sync(0xffffffffu, sum, d);
        if (t == 0) off_s = sum;
    }
    __syncthreads();
    const int off = off_s;

    int r = inc - s + (wid ? wsum[wid - 1] : 0) + off;   // global exclusive prefix
    if (base + 0 < NN) { g_rowptr[base + 0] = r; g_cursor[base + 0] = r; }  r += v.x;
    if (base + 1 < NN) { g_rowptr[base + 1] = r; g_cursor[base + 1] = r; }  r += v.y;
    if (base + 2 < NN) { g_rowptr[base + 2] = r; g_cursor[base + 2] = r; }  r += v.z;
    if (base + 3 < NN) { g_rowptr[base + 3] = r; g_cursor[base + 3] = r; }
    if (b == 0 && t == 0) g_rowptr[NN] = EE;
}

// ---------------------------------------------------------------------------
// Fill CSR src lists (1 edge/thread — max warp count hides ATOMG latency).
// Also re-zeroes g_deg for the NEXT launch (scan has already consumed it).
// ---------------------------------------------------------------------------
__global__ void fill_kernel(const int* __restrict__ ei) {
    int e = blockIdx.x * blockDim.x + threadIdx.x;
    if (e < NN) g_deg[e] = 0;   // restore invariant for next launch
    if (e >= EE) return;
    int s = ei[e];
    int d = ei[EE + e];
    int pos = atomicAdd(&g_cursor[d], 1);
    g_srclist[pos] = s;
}

// ---------------------------------------------------------------------------
// Aggregation as gather (fp16 in, fp32 accum, fp16 out), unroll-4:
// one warp per node, each lane owns 4 features (8B per edge per lane).
// ---------------------------------------------------------------------------
__global__ void gather_kernel(int sel) {
    int gid = blockIdx.x * blockDim.x + threadIdx.x;
    int node = gid >> 5;
    int lane = gid & 31;
    if (node >= NN) return;
    const __half* h = sel_buf_h(sel);

    int beg = g_rowptr[node];
    int end = g_rowptr[node + 1];
    float2 accA = make_float2(0.f, 0.f);
    float2 accB = make_float2(0.f, 0.f);
    int p = beg;
    for (; p + 4 <= end; p += 4) {
        int s0 = g_srclist[p],     s1 = g_srclist[p + 1];
        int s2 = g_srclist[p + 2], s3 = g_srclist[p + 3];
        uint2 v0 = *reinterpret_cast<const uint2*>(h + (size_t)s0 * HH + lane * 4);
        uint2 v1 = *reinterpret_cast<const uint2*>(h + (size_t)s1 * HH + lane * 4);
        uint2 v2 = *reinterpret_cast<const uint2*>(h + (size_t)s2 * HH + lane * 4);
        uint2 v3 = *reinterpret_cast<const uint2*>(h + (size_t)s3 * HH + lane * 4);
        float2 a0 = __half22float2(*(__half2*)&v0.x), a1 = __half22float2(*(__half2*)&v0.y);
        float2 b0 = __half22float2(*(__half2*)&v1.x), b1 = __half22float2(*(__half2*)&v1.y);
        float2 c0 = __half22float2(*(__half2*)&v2.x), c1 = __half22float2(*(__half2*)&v2.y);
        float2 d0 = __half22float2(*(__half2*)&v3.x), d1 = __half22float2(*(__half2*)&v3.y);
        accA.x += (a0.x + b0.x) + (c0.x + d0.x);
        accA.y += (a0.y + b0.y) + (c0.y + d0.y);
        accB.x += (a1.x + b1.x) + (c1.x + d1.x);
        accB.y += (a1.y + b1.y) + (c1.y + d1.y);
    }
    for (; p < end; p++) {
        int s0 = g_srclist[p];
        uint2 v0 = *reinterpret_cast<const uint2*>(h + (size_t)s0 * HH + lane * 4);
        float2 a0 = __half22float2(*(__half2*)&v0.x);
        float2 a1 = __half22float2(*(__half2*)&v0.y);
        accA.x += a0.x;  accA.y += a0.y;
        accB.x += a1.x;  accB.y += a1.y;
    }
    __half2 o0 = __floats2half2_rn(accA.x, accA.y);
    __half2 o1 = __floats2half2_rn(accB.x, accB.y);
    uint2 o = make_uint2(*(u32*)&o0, *(u32*)&o1);
    *reinterpret_cast<uint2*>(g_aggh + (size_t)node * HH + lane * 4) = o;
}

// ---------------------------------------------------------------------------
// Tensor-core layer GEMM (fp16 mma.sync m16n8k16, fp32 accum):
// out = ( [agg | h] @ [wr ; wroot] + b_rel ) * node_scale   (fp16 out)
// Block 256 thr = 8 warps (4 M x 2 N). M-tile 128, N=128, K=256 in 8 chunks
// of 32 (2 k16 steps each). Per warp: 2 M-frags x 8 N-frags.
// ---------------------------------------------------------------------------
__global__ void __launch_bounds__(256)
gemm_layer_mma(int in_sel, int out_sel, int layer,
               const float* __restrict__ brel,
               const int* __restrict__ batch) {
    __shared__ __half As[128][40];   // 32 data + 8 pad halves
    __shared__ __half Bs[128][40];

    const __half* h   = sel_buf_h(in_sel);
    __half*       out = (out_sel == 0) ? (__half*)g_h0 : (__half*)g_h1;

    const int tid  = threadIdx.x;
    const int wid  = tid >> 5, lane = tid & 31;
    const int g    = lane >> 2, t4 = lane & 3;
    const int wm   = wid & 3,  wn  = wid >> 2;
    const int row0 = blockIdx.x * MT;
    const int mbase = wm * 32;
    const int nbase = wn * 64;

    float acc[2][8][4];
#pragma unroll
    for (int mf = 0; mf < 2; mf++)
#pragma unroll
        for (int nf = 0; nf < 8; nf++)
#pragma unroll
            for (int q = 0; q < 4; q++) acc[mf][nf][q] = 0.f;

    for (int c = 0; c < 8; c++) {
        const __half* asrc = (c < 4) ? (const __half*)g_aggh : h;
        const __half* bsrc = &g_wTh[layer * 2 + (c < 4 ? 0 : 1)][0];
        const int ks = (c & 3) * 32;

        __syncthreads();
        // A chunk: 128 rows x 32 halves (64B/row) = 512 x 16B, 2 per thread
#pragma unroll
        for (int i = 0; i < 2; i++) {
            int f = tid + i * 256;           // 0..511
            int r = f >> 2, q = f & 3;       // row, 16B unit
            uint4 v = make_uint4(0, 0, 0, 0);
            if (row0 + r < NN)
                v = *reinterpret_cast<const uint4*>(asrc + (size_t)(row0 + r) * HH + ks + q * 8);
            *reinterpret_cast<uint4*>(&As[r][q * 8]) = v;
        }
        // B chunk: 128 n-rows x 32 k-halves from [n][k] fp16 weights
#pragma unroll
        for (int i = 0; i < 2; i++) {
            int f = tid + i * 256;
            int r = f >> 2, q = f & 3;
            uint4 v = *reinterpret_cast<const uint4*>(bsrc + (size_t)r * HH + ks + q * 8);
            *reinterpret_cast<uint4*>(&Bs[r][q * 8]) = v;
        }
        __syncthreads();

#pragma unroll
        for (int k16 = 0; k16 < 2; k16++) {
            const int kk = k16 * 16;
            u32 a[2][4];
#pragma unroll
            for (int mf = 0; mf < 2; mf++) {
                int rm = mbase + mf * 16;
                a[mf][0] = *(const u32*)&As[rm + g][kk + 2 * t4];
                a[mf][1] = *(const u32*)&As[rm + g + 8][kk + 2 * t4];
                a[mf][2] = *(const u32*)&As[rm + g][kk + 2 * t4 + 8];
                a[mf][3] = *(const u32*)&As[rm + g + 8][kk + 2 * t4 + 8];
            }
#pragma unroll
            for (int nf = 0; nf < 8; nf++) {
                int nrow = nbase + nf * 8 + g;
                u32 b0 = *(const u32*)&Bs[nrow][kk + 2 * t4];
                u32 b1 = *(const u32*)&Bs[nrow][kk + 2 * t4 + 8];
                mma_f16(acc[0][nf], a[0], b0, b1);
                mma_f16(acc[1][nf], a[1], b0, b1);
            }
        }
    }

    // Epilogue: +bias, *node_scale (fp32), convert to fp16, 4B stores
#pragma unroll
    for (int mf = 0; mf < 2; mf++) {
        int r0 = row0 + mbase + mf * 16 + g;
        int r1 = r0 + 8;
        float s0 = 0.f, s1 = 0.f;
        if (r0 < NN) { float cnt = g_counts[batch[r0]]; s0 = (cnt > 0.f) ? (1.f / cnt) : 0.f; }
        if (r1 < NN) { float cnt = g_counts[batch[r1]]; s1 = (cnt > 0.f) ? (1.f / cnt) : 0.f; }
#pragma unroll
        for (int nf = 0; nf < 8; nf++) {
            int col = nbase + nf * 8 + t4 * 2;
            float b0 = __ldg(&brel[col]), b1 = __ldg(&brel[col + 1]);
            if (r0 < NN) {
                __half2 o = __floats2half2_rn((acc[mf][nf][0] + b0) * s0,
                                              (acc[mf][nf][1] + b1) * s0);
                *reinterpret_cast<__half2*>(out + (size_t)r0 * HH + col) = o;
            }
            if (r1 < NN) {
                __half2 o = __floats2half2_rn((acc[mf][nf][2] + b0) * s1,
                                              (acc[mf][nf][3] + b1) * s1);
                *reinterpret_cast<__half2*>(out + (size_t)r1 * HH + col) = o;
            }
        }
    }
}

// ---------------------------------------------------------------------------
// Fused head: mean-pool (fp16 in, fp32 accum), relu MLP, log_softmax.
// ---------------------------------------------------------------------------
__global__ void __launch_bounds__(HH)
head_kernel(int sel,
            const float* __restrict__ w1, const float* __restrict__ b1,
            const float* __restrict__ w2, const float* __restrict__ b2,
            float* __restrict__ out) {
    __shared__ float p[HH];
    __shared__ float hv[HH];
    __shared__ float lg[CC];
    __shared__ float m_s, ls_s;

    const int g = blockIdx.x;
    const int tid = threadIdx.x;
    const __half* h = sel_buf_h(sel);

    int lo = g_gstart[g], hi = g_gstart[g + 1];
    float inv = (hi > lo) ? (1.f / (float)(hi - lo)) : 0.f;
    float acc0 = 0.f;
    for (int r = lo; r < hi; r++) acc0 += __half2float(h[(size_t)r * HH + tid]);
    p[tid] = acc0 * inv;
    __syncthreads();

    float acc = b1[tid];
#pragma unroll 8
    for (int k = 0; k < HH; k++) acc += p[k] * w1[k * HH + tid];
    hv[tid] = fmaxf(acc, 0.f);
    __syncthreads();

    if (tid < CC) {
        float l = b2[tid];
#pragma unroll 8
        for (int k = 0; k < HH; k++) l += hv[k] * w2[k * CC + tid];
        lg[tid] = l;
    }
    __syncthreads();

    if (tid == 0) {
        float m = lg[0];
#pragma unroll
        for (int i = 1; i < CC; i++) m = fmaxf(m, lg[i]);
        float s = 0.f;
#pragma unroll
        for (int i = 0; i < CC; i++) s += expf(lg[i] - m);
        m_s = m;
        ls_s = logf(s);
    }
    __syncthreads();
    if (tid < CC) out[g * CC + tid] = lg[tid] - m_s - ls_s;
}

// ---------------------------------------------------------------------------
extern "C" void kernel_launch(void* const* d_in, const int* in_sizes, int n_in,
                              void* d_out, int out_size) {
    const float* x      = (const float*)d_in[0];
    const int*   ei     = (const int*)d_in[1];
    const int*   batch  = (const int*)d_in[2];
    const float* w_rel  = (const float*)d_in[3];
    const float* b_rel  = (const float*)d_in[4];
    const float* w_root = (const float*)d_in[5];
    const float* w1     = (const float*)d_in[6];
    const float* b1     = (const float*)d_in[7];
    const float* w2     = (const float*)d_in[8];
    const float* b2     = (const float*)d_in[9];
    float* out = (float*)d_out;

    // Prep: x->fp16, weights->fp16 transposed, degree histogram, bounds.
    prep_kernel<<<NB_PREP, 256>>>(x, w_rel, w_root, ei, batch);

    // CSR: single-pass scan, then fill (fill also re-zeros g_deg for next call)
    scan_kernel<<<SNB, SB>>>();
    fill_kernel<<<(EE + 255) / 256, 256>>>(ei);

    // 3 GraphConv layers (sel: -1 = x(fp16), 0 = g_h0, 1 = g_h1)
    int cur_sel = -1;
    for (int l = 0; l < LL; l++) {
        gather_kernel<<<(NN * 32 + 255) / 256, 256>>>(cur_sel);
        int out_sel = l & 1;
        gemm_layer_mma<<<GEMM_BLOCKS, 256>>>(cur_sel, out_sel, l,
                                             b_rel + (size_t)l * HH, batch);
        cur_sel = out_sel;
    }

    // Fused mean-pool + MLP head
    head_kernel<<<GG, HH>>>(cur_sel, w1, b1, w2, b2, out);
}